// round 12
// baseline (speedup 1.0000x reference)
#include <cuda_runtime.h>

#define NPTS  8192
#define TPB   512
#define NC    10
#define NCELL 100
#define CAP   192          // own-cell capacity (mean 82; Poisson tail @192 ~ 0)
#define NOWN  (CAP + 8)    // padded for 4-wide self-pair access
#define NSH   (4 * CAP)    // shell capacity (mean ~330)
#define MIN_DISTF 0.1f

// scratch (module-load zero-init; last block resets g_cnt each launch)
__device__ float g_pen[NCELL];
__device__ float g_mse[NCELL];
__device__ int   g_cnt = 0;

__device__ __forceinline__ float rsq(float x) {
    float r;
    asm("rsqrt.approx.f32 %0, %1;" : "=f"(r) : "f"(x));
    return r;
}

// branchless pair: d2<=0 or d>=0.1 (incl. 1e9 sentinels) contribute exactly 0
#define PAIR(xi, yi, xj, yj, acc)                          \
    {                                                      \
        float dx_ = (xi) - (xj), dy_ = (yi) - (yj);        \
        float d2_ = fmaf(dx_, dx_, dy_ * dy_);             \
        float r_  = rsq(d2_);                              \
        float m_  = fmaxf(fmaf(d2_, -r_, MIN_DISTF), 0.f); \
        (acc) = fmaf(m_, m_, (acc));                       \
    }

__global__ void __launch_bounds__(TPB) k_all(const float2* __restrict__ pts,
                                             const float2* __restrict__ tg,
                                             float* __restrict__ out) {
    __shared__ __align__(16) float sOx[NOWN];
    __shared__ __align__(16) float sOy[NOWN];
    __shared__ __align__(16) float sNx[NSH];
    __shared__ __align__(16) float sNy[NSH];
    __shared__ int   cntO, cntN;
    __shared__ float smP[TPB / 32];
    __shared__ float smM[TPB / 32];
    __shared__ int   lastFlag;

    const int tid  = threadIdx.x;
    const int b    = blockIdx.x;
    const int cx   = b % NC, cy = b / NC;
    const int lane = tid & 31, w = tid >> 5;

    if (tid == 0) { cntO = 0; cntN = 0; }
    __syncthreads();

    // ---- scan ALL points (L2-resident); warp-aggregated compaction ----
    // exactly 16 full iterations per thread -> ballots are warp-uniform
    for (int k = tid; k < NPTS; k += TPB) {
        float2 q  = pts[k];
        int qcx = (int)(q.x * 10.f); qcx = qcx > 9 ? 9 : qcx;
        int qcy = (int)(q.y * 10.f); qcy = qcy > 9 ? 9 : qcy;
        int dx = qcx - cx, dy = qcy - cy;
        bool own   = (dx | dy) == 0;
        // half shell: (+1,0), (-1,+1), (0,+1), (+1,+1)  (antisymmetric set)
        bool shell = (dy == 0 && dx == 1) || (dy == 1 && (unsigned)(dx + 1) <= 2u);

        unsigned mo = __ballot_sync(0xffffffffu, own);
        unsigned ms = __ballot_sync(0xffffffffu, shell);
        int baseO = 0, baseS = 0;
        if (lane == 0) {
            if (mo) baseO = atomicAdd(&cntO, __popc(mo));
            if (ms) baseS = atomicAdd(&cntN, __popc(ms));
        }
        baseO = __shfl_sync(0xffffffffu, baseO, 0);
        baseS = __shfl_sync(0xffffffffu, baseS, 0);
        unsigned below = (1u << lane) - 1u;
        if (own) {
            int s = baseO + __popc(mo & below);
            if (s < CAP) { sOx[s] = q.x; sOy[s] = q.y; }
        } else if (shell) {
            int s = baseS + __popc(ms & below);
            if (s < NSH) { sNx[s] = q.x; sNy[s] = q.y; }
        }
    }

    // ---- MSE slice: 82 points per block (100*82 >= 8192, guarded) ----
    float mse = 0.f;
    if (tid < 82) {
        int i = b * 82 + tid;
        if (i < NPTS) {
            float2 p = pts[i];
            float2 t = tg[i];
            float dx = p.x - t.x, dy = p.y - t.y;
            mse = fmaf(dx, dx, dy * dy);
        }
    }
    __syncthreads();

    const int nO  = cntO > CAP ? CAP : cntO;
    const int nN  = cntN > NSH ? NSH : cntN;
    const int nor = (nO + 3) & ~3;
    // pad own tile tail with far sentinels for the 4-wide loops
    for (int k = nO + tid; k < nor + 4; k += TPB) { sOx[k] = 1e9f; sOy[k] = 1e9f; }
    __syncthreads();

    const float4* ox4 = reinterpret_cast<const float4*>(sOx);
    const float4* oy4 = reinterpret_cast<const float4*>(sOy);
    const int     ni4 = nor >> 2;

    float a0 = 0.f, a1 = 0.f, a2 = 0.f, a3 = 0.f;

    // cross pairs: each thread takes shell candidates strided, 4 indep chains over own
    for (int j = tid; j < nN; j += TPB) {
        float xj = sNx[j], yj = sNy[j];
        for (int i4 = 0; i4 < ni4; i4++) {
            float4 qx = ox4[i4];
            float4 qy = oy4[i4];
            PAIR(qx.x, qy.x, xj, yj, a0);
            PAIR(qx.y, qy.y, xj, yj, a1);
            PAIR(qx.z, qy.z, xj, yj, a2);
            PAIR(qx.w, qy.w, xj, yj, a3);
        }
    }

    // self pairs: slot order i<j, 4-wide over sentinel-padded tail
    if (tid < nO) {
        const float xi = sOx[tid], yi = sOy[tid];
        for (int j = tid + 1; j < nor; j += 4) {
            PAIR(xi, yi, sOx[j + 0], sOy[j + 0], a0);
            PAIR(xi, yi, sOx[j + 1], sOy[j + 1], a1);
            PAIR(xi, yi, sOx[j + 2], sOy[j + 2], a2);
            PAIR(xi, yi, sOx[j + 3], sOy[j + 3], a3);
        }
    }

    // ---- block reduction (pen, mse) ----
    float pen = (a0 + a1) + (a2 + a3);
#pragma unroll
    for (int o = 16; o > 0; o >>= 1) {
        pen += __shfl_xor_sync(0xffffffffu, pen, o);
        mse += __shfl_xor_sync(0xffffffffu, mse, o);
    }
    if (lane == 0) { smP[w] = pen; smM[w] = mse; }
    __syncthreads();
    if (tid == 0) {
        float ps = 0.f, ms = 0.f;
#pragma unroll
        for (int x = 0; x < TPB / 32; x++) { ps += smP[x]; ms += smM[x]; }
        g_pen[b] = ps;
        g_mse[b] = ms;
        __threadfence();
        int ticket = atomicAdd(&g_cnt, 1);
        lastFlag = (ticket == NCELL - 1);
    }
    __syncthreads();

    // ---- last block: deterministic fp64 final reduction ----
    if (lastFlag && w == 0) {
        double pd = 0.0, md = 0.0;
#pragma unroll
        for (int x = 0; x < 4; x++) {
            int idx = lane + x * 32;
            if (idx < NCELL) {
                pd += (double)__ldcg(&g_pen[idx]);
                md += (double)__ldcg(&g_mse[idx]);
            }
        }
#pragma unroll
        for (int o = 16; o > 0; o >>= 1) {
            pd += __shfl_xor_sync(0xffffffffu, pd, o);
            md += __shfl_xor_sync(0xffffffffu, md, o);
        }
        if (lane == 0) {
            out[0] = (float)(md * (1.0 / (double)(NPTS * 2)) + pd);
            g_cnt  = 0;
        }
    }
}

extern "C" void kernel_launch(void* const* d_in, const int* in_sizes, int n_in,
                              void* d_out, int out_size) {
    const float2* pred = (const float2*)d_in[0];
    const float2* targ = (const float2*)d_in[1];
    k_all<<<NCELL, TPB>>>(pred, targ, (float*)d_out);
}

// round 13
// speedup vs baseline: 1.2959x; 1.2959x over previous
#include <cuda_runtime.h>

#define NPTS  8192
#define TPB   512
#define PPT   16           // points per thread (512*16 = 8192 exactly)
#define NC    10
#define NCELL 100
#define CAP   192          // own-cell capacity (mean 82)
#define NOWN  (CAP + 8)
#define NSH   (4 * CAP)    // shell capacity (mean ~330)
#define MIN_DISTF 0.1f

// scratch (module-load zero-init; last block resets g_cnt each launch)
__device__ float g_pen[NCELL];
__device__ float g_mse[NCELL];
__device__ int   g_cnt = 0;

__device__ __forceinline__ float rsq(float x) {
    float r;
    asm("rsqrt.approx.f32 %0, %1;" : "=f"(r) : "f"(x));
    return r;
}

// branchless pair: d2<=0 or d>=0.1 (incl. 1e9 sentinels) contribute exactly 0
#define PAIR(xi, yi, xj, yj, acc)                          \
    {                                                      \
        float dx_ = (xi) - (xj), dy_ = (yi) - (yj);        \
        float d2_ = fmaf(dx_, dx_, dy_ * dy_);             \
        float r_  = rsq(d2_);                              \
        float m_  = fmaxf(fmaf(d2_, -r_, MIN_DISTF), 0.f); \
        (acc) = fmaf(m_, m_, (acc));                       \
    }

__global__ void __launch_bounds__(TPB) k_all(const float2* __restrict__ pts,
                                             const float2* __restrict__ tg,
                                             float* __restrict__ out) {
    __shared__ __align__(16) float sOx[NOWN];
    __shared__ __align__(16) float sOy[NOWN];
    __shared__ __align__(16) float sNx[NSH];
    __shared__ __align__(16) float sNy[NSH];
    __shared__ int   smW[TPB / 32];      // warp scan totals
    __shared__ int   totals;             // packed (own | shell<<16) block totals
    __shared__ float smP[TPB / 32];
    __shared__ float smM[TPB / 32];
    __shared__ int   lastFlag;

    const int tid  = threadIdx.x;
    const int b    = blockIdx.x;
    const int cx   = b % NC, cy = b / NC;
    const int lane = tid & 31, w = tid >> 5;

    // ---- Phase A1: prefetch 16 points as 8 independent LDG.128 (MLP=8) ----
    const float4* p4 = reinterpret_cast<const float4*>(pts);
    float4 r[PPT / 2];
#pragma unroll
    for (int t = 0; t < PPT / 2; t++) r[t] = p4[tid + t * TPB];  // 2 pts each

    // ---- Phase A2: classify in registers (pure ALU) ----
    unsigned ownM = 0, shM = 0;
    int co = 0, cs = 0;
#pragma unroll
    for (int t = 0; t < PPT; t++) {
        float qx = (t & 1) ? r[t >> 1].z : r[t >> 1].x;
        float qy = (t & 1) ? r[t >> 1].w : r[t >> 1].y;
        int qcx = (int)(qx * 10.f); qcx = qcx > 9 ? 9 : qcx;
        int qcy = (int)(qy * 10.f); qcy = qcy > 9 ? 9 : qcy;
        int dx = qcx - cx, dy = qcy - cy;
        bool own   = (dx | dy) == 0;
        // half shell: (+1,0), (-1,+1), (0,+1), (+1,+1) (antisymmetric set)
        bool shell = (dy == 0 && dx == 1) || (dy == 1 && (unsigned)(dx + 1) <= 2u);
        ownM |= own   ? (1u << t) : 0u;
        shM  |= shell ? (1u << t) : 0u;
        co += own;
        cs += shell;
    }

    // ---- Phase A3: ONE block exclusive scan of packed (co | cs<<16) ----
    int val = co | (cs << 16);
    int inc = val;
#pragma unroll
    for (int o = 1; o < 32; o <<= 1) {
        int y = __shfl_up_sync(0xffffffffu, inc, o);
        if (lane >= o) inc += y;
    }
    if (lane == 31) smW[w] = inc;            // warp inclusive total
    int pre = inc - val;                      // intra-warp exclusive
    __syncthreads();
    if (w == 0) {
        int t = (lane < TPB / 32) ? smW[lane] : 0;
        int ti = t;
#pragma unroll
        for (int o = 1; o < 32; o <<= 1) {
            int y = __shfl_up_sync(0xffffffffu, ti, o);
            if (lane >= o) ti += y;
        }
        if (lane < TPB / 32) smW[lane] = ti - t;   // warp-base exclusive
        if (lane == TPB / 32 - 1) totals = ti;     // block totals
    }
    __syncthreads();
    int base  = smW[w] + pre;
    int oo    = base & 0xffff;
    int ss    = base >> 16;
    const int nOt = totals & 0xffff;
    const int nNt = totals >> 16;

    // ---- Phase A4: write hits at exact offsets (no atomics) ----
#pragma unroll
    for (int t = 0; t < PPT; t++) {
        if (ownM & (1u << t)) {
            if (oo < CAP) {
                sOx[oo] = (t & 1) ? r[t >> 1].z : r[t >> 1].x;
                sOy[oo] = (t & 1) ? r[t >> 1].w : r[t >> 1].y;
            }
            oo++;
        } else if (shM & (1u << t)) {
            if (ss < NSH) {
                sNx[ss] = (t & 1) ? r[t >> 1].z : r[t >> 1].x;
                sNy[ss] = (t & 1) ? r[t >> 1].w : r[t >> 1].y;
            }
            ss++;
        }
    }

    // ---- MSE slice: 82 points per block (guarded) ----
    float mse = 0.f;
    if (tid < 82) {
        int i = b * 82 + tid;
        if (i < NPTS) {
            float2 p = pts[i];
            float2 t2 = tg[i];
            float dx = p.x - t2.x, dy = p.y - t2.y;
            mse = fmaf(dx, dx, dy * dy);
        }
    }

    const int nO  = nOt > CAP ? CAP : nOt;
    const int nN  = nNt > NSH ? NSH : nNt;
    const int nor = (nO + 3) & ~3;
    __syncthreads();
    // pad own tile tail with far sentinels for the 4-wide loops
    for (int k = nO + tid; k < nor + 4; k += TPB) { sOx[k] = 1e9f; sOy[k] = 1e9f; }
    __syncthreads();

    const float4* ox4 = reinterpret_cast<const float4*>(sOx);
    const float4* oy4 = reinterpret_cast<const float4*>(sOy);
    const int     ni4 = nor >> 2;

    float a0 = 0.f, a1 = 0.f, a2 = 0.f, a3 = 0.f;

    // cross pairs: each thread takes shell candidates strided, 4 indep chains
    for (int j = tid; j < nN; j += TPB) {
        float xj = sNx[j], yj = sNy[j];
        for (int i4 = 0; i4 < ni4; i4++) {
            float4 qx = ox4[i4];
            float4 qy = oy4[i4];
            PAIR(qx.x, qy.x, xj, yj, a0);
            PAIR(qx.y, qy.y, xj, yj, a1);
            PAIR(qx.z, qy.z, xj, yj, a2);
            PAIR(qx.w, qy.w, xj, yj, a3);
        }
    }

    // self pairs: slot order i<j, 4-wide over sentinel-padded tail
    if (tid < nO) {
        const float xi = sOx[tid], yi = sOy[tid];
        for (int j = tid + 1; j < nor; j += 4) {
            PAIR(xi, yi, sOx[j + 0], sOy[j + 0], a0);
            PAIR(xi, yi, sOx[j + 1], sOy[j + 1], a1);
            PAIR(xi, yi, sOx[j + 2], sOy[j + 2], a2);
            PAIR(xi, yi, sOx[j + 3], sOy[j + 3], a3);
        }
    }

    // ---- block reduction (pen, mse) ----
    float pen = (a0 + a1) + (a2 + a3);
#pragma unroll
    for (int o = 16; o > 0; o >>= 1) {
        pen += __shfl_xor_sync(0xffffffffu, pen, o);
        mse += __shfl_xor_sync(0xffffffffu, mse, o);
    }
    if (lane == 0) { smP[w] = pen; smM[w] = mse; }
    __syncthreads();
    if (tid == 0) {
        float ps = 0.f, ms = 0.f;
#pragma unroll
        for (int x = 0; x < TPB / 32; x++) { ps += smP[x]; ms += smM[x]; }
        g_pen[b] = ps;
        g_mse[b] = ms;
        __threadfence();
        int ticket = atomicAdd(&g_cnt, 1);
        lastFlag = (ticket == NCELL - 1);
    }
    __syncthreads();

    // ---- last block: deterministic fp64 final reduction ----
    if (lastFlag && w == 0) {
        double pd = 0.0, md = 0.0;
#pragma unroll
        for (int x = 0; x < 4; x++) {
            int idx = lane + x * 32;
            if (idx < NCELL) {
                pd += (double)__ldcg(&g_pen[idx]);
                md += (double)__ldcg(&g_mse[idx]);
            }
        }
#pragma unroll
        for (int o = 16; o > 0; o >>= 1) {
            pd += __shfl_xor_sync(0xffffffffu, pd, o);
            md += __shfl_xor_sync(0xffffffffu, md, o);
        }
        if (lane == 0) {
            out[0] = (float)(md * (1.0 / (double)(NPTS * 2)) + pd);
            g_cnt  = 0;
        }
    }
}

extern "C" void kernel_launch(void* const* d_in, const int* in_sizes, int n_in,
                              void* d_out, int out_size) {
    const float2* pred = (const float2*)d_in[0];
    const float2* targ = (const float2*)d_in[1];
    k_all<<<NCELL, TPB>>>(pred, targ, (float*)d_out);
}